// round 17
// baseline (speedup 1.0000x reference)
#include <cuda_runtime.h>
#include <cstddef>

// Problem constants (fixed shapes from reference setup_inputs)
#define T_STEPS 16
#define B_SZ    512
#define F_IN    2048
#define H_SZ    2048
#define OUT_SZ  1024
#define BT      (B_SZ * T_STEPS)   // 8192

// Pipeline grouping: 4 groups x 4 timesteps
#define N_GROUPS 4
#define T_PER_G  (T_STEPS / N_GROUPS)          // 4
#define ROWS_PER_G (T_PER_G * B_SZ)            // 2048

// Scratch (device globals: allocation-free per harness rules)
// g_H is T-MAJOR: g_H[((t * B_SZ) + b) * H_SZ + h]
__device__ float g_H  [ (size_t)BT  * H_SZ   ];   // 64 MB
__device__ float g_v1 [ (size_t)B_SZ * H_SZ  ];   // membrane lif1
__device__ float g_v2 [ (size_t)B_SZ * OUT_SZ];   // membrane lif_out
__device__ float g_W2T[ (size_t)H_SZ * OUT_SZ];   // 8 MB: W2 transposed [H, OUT]

// ---------------------------------------------------------------------------
// init: zero membranes
// ---------------------------------------------------------------------------
__global__ void init_state_kernel() {
    size_t i = (size_t)blockIdx.x * blockDim.x + threadIdx.x;
    size_t n1 = (size_t)B_SZ * H_SZ;
    size_t n2 = (size_t)B_SZ * OUT_SZ;
    if (i < n1) g_v1[i] = 0.0f;
    if (i < n2) g_v2[i] = 0.0f;
}

// ---------------------------------------------------------------------------
// Transpose W2 [OUT, H] -> W2T [H, OUT].  32x32 smem tiles.
// ---------------------------------------------------------------------------
__global__ void transpose_w2_kernel(const float* __restrict__ W2)
{
    __shared__ float tile[32][33];
    int o0 = blockIdx.y * 32;
    int k0 = blockIdx.x * 32;
    int tx = threadIdx.x, ty = threadIdx.y;   // 32 x 8

    #pragma unroll
    for (int r = 0; r < 32; r += 8)
        tile[ty + r][tx] = W2[(size_t)(o0 + ty + r) * H_SZ + k0 + tx];
    __syncthreads();
    #pragma unroll
    for (int r = 0; r < 32; r += 8)
        g_W2T[(size_t)(k0 + ty + r) * OUT_SZ + o0 + tx] = tile[tx][ty + r];
}

// ---------------------------------------------------------------------------
// GEMM1 phase kernel — R13 config + R17 register fragment double-buffering.
// ACCUMULATION CONTRACT (frozen, R6): per element, 2 contiguous K-chunks of
// 1024, each a serial ascending FMA chain from zero, merged sequentially.
//   Phase A (ACCUM=false): C = chain(K[0:1024])
//   Phase B (ACCUM=true):  C = __fadd_rn(C, chain(K[1024:2048]))
// R17 changes (load scheduling ONLY — per-element FMA order identical):
//  - fragments for k+1 prefetched into registers while computing k
//  - staging STS moved to mid-tile (k=8) to shorten staging live range
// Output row m (t-major: m = t*512 + b) reads x row (b*16 + t).
// ---------------------------------------------------------------------------
#define G1_BM 128
#define G1_BN 128
#define G1_BK 16
#define G1_KC 1024
#define G1_NT (G1_KC / G1_BK)   // 64 tiles per phase

__device__ __forceinline__ int x_row_of(int m) {
    // m = t*512 + b  ->  x row = b*16 + t
    return ((m & (B_SZ - 1)) << 4) + (m >> 9);
}

template<bool ACCUM>
__global__ __launch_bounds__(256, 2)
void gemm1_phase_kernel(const float* __restrict__ A,    // x   [BT, F_IN] (b-major)
                        const float* __restrict__ Bm,   // W1  [H, F_IN]
                        float* __restrict__ C,          // g_H [BT, H] (t-major)
                        int k_base, int m_base)
{
    __shared__ float As[2][G1_BK][G1_BM];
    __shared__ float Bs[2][G1_BK][G1_BN];

    const int tid  = threadIdx.x;
    const int m0   = m_base + blockIdx.y * G1_BM;
    const int n0   = blockIdx.x * G1_BN;

    // Strided-fragment mapping: warp 8x4, CTA warps 2x4.
    const int lane = tid & 31;
    const int warp = tid >> 5;
    const int ly   = lane >> 2;          // 0..7
    const int lx   = lane & 3;           // 0..3
    const int wy   = warp >> 2;          // 0..1
    const int wx   = warp & 3;           // 0..3
    const int rr   = (wy * 8 + ly) * 4;  // row base
    const int cc   = (wx * 4 + lx) * 4;  // col base

    // Staging (global->smem) mapping.
    const int r0 = tid >> 2;
    const int c0 = tid & 3;
    const int r1 = (tid + 256) >> 2;
    const int c1 = (tid + 256) & 3;

    const float* Arow0 = A  + (size_t)x_row_of(m0 + r0) * F_IN + k_base + c0 * 4;
    const float* Arow1 = A  + (size_t)x_row_of(m0 + r1) * F_IN + k_base + c1 * 4;
    const float* Brow0 = Bm + (size_t)(n0 + r0) * F_IN + k_base + c0 * 4;
    const float* Brow1 = Bm + (size_t)(n0 + r1) * F_IN + k_base + c1 * 4;

    float acc[8][8];
    #pragma unroll
    for (int i = 0; i < 8; i++)
        #pragma unroll
        for (int j = 0; j < 8; j++)
            acc[i][j] = 0.0f;

    float4 ra0, ra1, rb0, rb1;

    // Prologue: tile 0 -> buffer 0
    ra0 = *reinterpret_cast<const float4*>(Arow0);
    ra1 = *reinterpret_cast<const float4*>(Arow1);
    rb0 = *reinterpret_cast<const float4*>(Brow0);
    rb1 = *reinterpret_cast<const float4*>(Brow1);
    As[0][c0*4+0][r0] = ra0.x; As[0][c0*4+1][r0] = ra0.y;
    As[0][c0*4+2][r0] = ra0.z; As[0][c0*4+3][r0] = ra0.w;
    As[0][c1*4+0][r1] = ra1.x; As[0][c1*4+1][r1] = ra1.y;
    As[0][c1*4+2][r1] = ra1.z; As[0][c1*4+3][r1] = ra1.w;
    Bs[0][c0*4+0][r0] = rb0.x; Bs[0][c0*4+1][r0] = rb0.y;
    Bs[0][c0*4+2][r0] = rb0.z; Bs[0][c0*4+3][r0] = rb0.w;
    Bs[0][c1*4+0][r1] = rb1.x; Bs[0][c1*4+1][r1] = rb1.y;
    Bs[0][c1*4+2][r1] = rb1.z; Bs[0][c1*4+3][r1] = rb1.w;
    __syncthreads();

    float fa[2][8], fb[2][8];

    for (int kt = 0; kt < G1_NT; kt++) {
        const int buf = kt & 1;
        const int nb  = 1 - buf;
        const bool more = (kt + 1 < G1_NT);

        // Issue next tile's staging LDGs (consumed mid-loop at STS)
        if (more) {
            const int koff = (kt + 1) * G1_BK;
            ra0 = *reinterpret_cast<const float4*>(Arow0 + koff);
            ra1 = *reinterpret_cast<const float4*>(Arow1 + koff);
            rb0 = *reinterpret_cast<const float4*>(Brow0 + koff);
            rb1 = *reinterpret_cast<const float4*>(Brow1 + koff);
        }

        // Preload fragments for k=0
        {
            float4 a_lo = *reinterpret_cast<const float4*>(&As[buf][0][rr]);
            float4 a_hi = *reinterpret_cast<const float4*>(&As[buf][0][rr + 64]);
            float4 b_lo = *reinterpret_cast<const float4*>(&Bs[buf][0][cc]);
            float4 b_hi = *reinterpret_cast<const float4*>(&Bs[buf][0][cc + 64]);
            fa[0][0]=a_lo.x; fa[0][1]=a_lo.y; fa[0][2]=a_lo.z; fa[0][3]=a_lo.w;
            fa[0][4]=a_hi.x; fa[0][5]=a_hi.y; fa[0][6]=a_hi.z; fa[0][7]=a_hi.w;
            fb[0][0]=b_lo.x; fb[0][1]=b_lo.y; fb[0][2]=b_lo.z; fb[0][3]=b_lo.w;
            fb[0][4]=b_hi.x; fb[0][5]=b_hi.y; fb[0][6]=b_hi.z; fb[0][7]=b_hi.w;
        }

        // First half: k = 0..7 (prefetch k+1 fragments during FMA of k)
        #pragma unroll
        for (int k = 0; k < 8; k++) {
            const int cur = k & 1, nxt = cur ^ 1;
            {
                float4 a_lo = *reinterpret_cast<const float4*>(&As[buf][k+1][rr]);
                float4 a_hi = *reinterpret_cast<const float4*>(&As[buf][k+1][rr + 64]);
                float4 b_lo = *reinterpret_cast<const float4*>(&Bs[buf][k+1][cc]);
                float4 b_hi = *reinterpret_cast<const float4*>(&Bs[buf][k+1][cc + 64]);
                fa[nxt][0]=a_lo.x; fa[nxt][1]=a_lo.y; fa[nxt][2]=a_lo.z; fa[nxt][3]=a_lo.w;
                fa[nxt][4]=a_hi.x; fa[nxt][5]=a_hi.y; fa[nxt][6]=a_hi.z; fa[nxt][7]=a_hi.w;
                fb[nxt][0]=b_lo.x; fb[nxt][1]=b_lo.y; fb[nxt][2]=b_lo.z; fb[nxt][3]=b_lo.w;
                fb[nxt][4]=b_hi.x; fb[nxt][5]=b_hi.y; fb[nxt][6]=b_hi.z; fb[nxt][7]=b_hi.w;
            }
            #pragma unroll
            for (int i = 0; i < 8; i++)
                #pragma unroll
                for (int j = 0; j < 8; j++)
                    acc[i][j] = fmaf(fa[cur][i], fb[cur][j], acc[i][j]);
        }

        // Mid-tile: drain staging registers into the next buffer
        if (more) {
            As[nb][c0*4+0][r0] = ra0.x; As[nb][c0*4+1][r0] = ra0.y;
            As[nb][c0*4+2][r0] = ra0.z; As[nb][c0*4+3][r0] = ra0.w;
            As[nb][c1*4+0][r1] = ra1.x; As[nb][c1*4+1][r1] = ra1.y;
            As[nb][c1*4+2][r1] = ra1.z; As[nb][c1*4+3][r1] = ra1.w;
            Bs[nb][c0*4+0][r0] = rb0.x; Bs[nb][c0*4+1][r0] = rb0.y;
            Bs[nb][c0*4+2][r0] = rb0.z; Bs[nb][c0*4+3][r0] = rb0.w;
            Bs[nb][c1*4+0][r1] = rb1.x; Bs[nb][c1*4+1][r1] = rb1.y;
            Bs[nb][c1*4+2][r1] = rb1.z; Bs[nb][c1*4+3][r1] = rb1.w;
        }

        // Second half: k = 8..15
        #pragma unroll
        for (int k = 8; k < 16; k++) {
            const int cur = k & 1, nxt = cur ^ 1;
            if (k + 1 < 16) {
                float4 a_lo = *reinterpret_cast<const float4*>(&As[buf][k+1][rr]);
                float4 a_hi = *reinterpret_cast<const float4*>(&As[buf][k+1][rr + 64]);
                float4 b_lo = *reinterpret_cast<const float4*>(&Bs[buf][k+1][cc]);
                float4 b_hi = *reinterpret_cast<const float4*>(&Bs[buf][k+1][cc + 64]);
                fa[nxt][0]=a_lo.x; fa[nxt][1]=a_lo.y; fa[nxt][2]=a_lo.z; fa[nxt][3]=a_lo.w;
                fa[nxt][4]=a_hi.x; fa[nxt][5]=a_hi.y; fa[nxt][6]=a_hi.z; fa[nxt][7]=a_hi.w;
                fb[nxt][0]=b_lo.x; fb[nxt][1]=b_lo.y; fb[nxt][2]=b_lo.z; fb[nxt][3]=b_lo.w;
                fb[nxt][4]=b_hi.x; fb[nxt][5]=b_hi.y; fb[nxt][6]=b_hi.z; fb[nxt][7]=b_hi.w;
            }
            #pragma unroll
            for (int i = 0; i < 8; i++)
                #pragma unroll
                for (int j = 0; j < 8; j++)
                    acc[i][j] = fmaf(fa[cur][i], fb[cur][j], acc[i][j]);
        }
        __syncthreads();
    }

    // Epilogue: rows {rr+i, rr+64+i}, cols {cc..cc+3, cc+64..cc+67}
    #pragma unroll
    for (int i = 0; i < 8; i++) {
        const int row = m0 + ((i < 4) ? (rr + i) : (rr + 64 + i - 4));
        #pragma unroll
        for (int jh = 0; jh < 2; jh++) {
            const int col = n0 + cc + jh * 64;
            float* cp = C + (size_t)row * H_SZ + col;
            const int j0 = jh * 4;
            if (ACCUM) {
                float4 prev = *reinterpret_cast<const float4*>(cp);
                float4 v = make_float4(__fadd_rn(prev.x, acc[i][j0+0]),
                                       __fadd_rn(prev.y, acc[i][j0+1]),
                                       __fadd_rn(prev.z, acc[i][j0+2]),
                                       __fadd_rn(prev.w, acc[i][j0+3]));
                *reinterpret_cast<float4*>(cp) = v;
            } else {
                float4 v = make_float4(acc[i][j0+0], acc[i][j0+1],
                                       acc[i][j0+2], acc[i][j0+3]);
                *reinterpret_cast<float4*>(cp) = v;
            }
        }
    }
}

// ---------------------------------------------------------------------------
// Fused timestep kernel: LIF1 + ordered compaction (smem) + sparse GEMM2 +
// LIF2. One CTA (256 threads) per batch row b. Orders identical to R8-R16.
// ---------------------------------------------------------------------------
__global__ __launch_bounds__(256)
void step_kernel(int t, float* __restrict__ out_ch, float* __restrict__ out_com)
{
    __shared__ int sk[H_SZ];    // spike k-indices, ascending (8 KB)
    __shared__ int sc[256];     // scan workspace

    const int b   = blockIdx.x;
    const int tid = threadIdx.x;
    const int PER = H_SZ / 256;   // 8

    const size_t hbase  = ((size_t)t * B_SZ + b) * H_SZ + (size_t)tid * PER; // t-major
    const size_t chbase = ((size_t)b * T_STEPS + t) * H_SZ + (size_t)tid * PER;
    const size_t vbase  = (size_t)b * H_SZ + (size_t)tid * PER;

    float h[PER], v[PER];
    #pragma unroll
    for (int j = 0; j < PER; j += 4) {
        float4 hv = *reinterpret_cast<const float4*>(&g_H[hbase + j]);
        h[j] = hv.x; h[j+1] = hv.y; h[j+2] = hv.z; h[j+3] = hv.w;
        float4 vv = *reinterpret_cast<const float4*>(&g_v1[vbase + j]);
        v[j] = vv.x; v[j+1] = vv.y; v[j+2] = vv.z; v[j+3] = vv.w;
    }

    float s[PER];
    int cnt = 0;
    #pragma unroll
    for (int j = 0; j < PER; j++) {
        float nv = __fmul_rn(__fadd_rn(v[j], h[j]), 0.5f);   // single rounding
        s[j] = (nv >= 0.5f) ? 1.0f : 0.0f;
        v[j] = (s[j] != 0.0f) ? 0.0f : nv;
        cnt += (s[j] != 0.0f) ? 1 : 0;
    }

    #pragma unroll
    for (int j = 0; j < PER; j += 4) {
        *reinterpret_cast<float4*>(&out_ch[chbase + j]) =
            make_float4(s[j], s[j+1], s[j+2], s[j+3]);
        *reinterpret_cast<float4*>(&g_v1[vbase + j]) =
            make_float4(v[j], v[j+1], v[j+2], v[j+3]);
    }

    // block inclusive scan of counts
    sc[tid] = cnt;
    __syncthreads();
    #pragma unroll
    for (int off = 1; off < 256; off <<= 1) {
        int add = (tid >= off) ? sc[tid - off] : 0;
        __syncthreads();
        sc[tid] += add;
        __syncthreads();
    }
    int pos = sc[tid] - cnt;   // exclusive prefix

    #pragma unroll
    for (int j = 0; j < PER; j++)
        if (s[j] != 0.0f)
            sk[pos++] = tid * PER + j;

    const int total = sc[255];
    __syncthreads();   // sk fully written before reads

    // sparse GEMM2: ascending-k sum == dense serial FMA chain (bitwise)
    const int o = tid * 4;
    float a0 = 0.0f, a1 = 0.0f, a2 = 0.0f, a3 = 0.0f;

    #pragma unroll 4
    for (int i = 0; i < total; i++) {
        const int k = sk[i];
        float4 w = *reinterpret_cast<const float4*>(&g_W2T[(size_t)k * OUT_SZ + o]);
        a0 = __fadd_rn(a0, w.x);
        a1 = __fadd_rn(a1, w.y);
        a2 = __fadd_rn(a2, w.z);
        a3 = __fadd_rn(a3, w.w);
    }

    // LIF2 epilogue
    const size_t v2base = (size_t)b * OUT_SZ + o;
    float4 vv = *reinterpret_cast<const float4*>(&g_v2[v2base]);
    float acc[4] = {a0, a1, a2, a3};
    float vin[4] = {vv.x, vv.y, vv.z, vv.w};
    float sp[4], vout[4];
    #pragma unroll
    for (int j = 0; j < 4; j++) {
        float nv = __fmul_rn(__fadd_rn(vin[j], acc[j]), 0.5f);
        sp[j]   = (nv >= 0.5f) ? 1.0f : 0.0f;
        vout[j] = (sp[j] != 0.0f) ? 0.0f : nv;
    }
    *reinterpret_cast<float4*>(
        &out_com[((size_t)b * T_STEPS + t) * OUT_SZ + o]) =
        make_float4(sp[0], sp[1], sp[2], sp[3]);
    *reinterpret_cast<float4*>(&g_v2[v2base]) =
        make_float4(vout[0], vout[1], vout[2], vout[3]);
}

// ---------------------------------------------------------------------------
// Static streams + events (created once; identical graph every call).
// ---------------------------------------------------------------------------
struct PipeRes {
    cudaStream_t sA, sB;
    cudaEvent_t  ev_fork;
    cudaEvent_t  eA[N_GROUPS], eB[N_GROUPS];
    PipeRes() {
        cudaStreamCreateWithFlags(&sA, cudaStreamNonBlocking);
        cudaStreamCreateWithFlags(&sB, cudaStreamNonBlocking);
        cudaEventCreateWithFlags(&ev_fork, cudaEventDisableTiming);
        for (int g = 0; g < N_GROUPS; g++) {
            cudaEventCreateWithFlags(&eA[g], cudaEventDisableTiming);
            cudaEventCreateWithFlags(&eB[g], cudaEventDisableTiming);
        }
    }
};
static PipeRes g_pr;

// ---------------------------------------------------------------------------
// kernel_launch: graph-capturable, allocation-free.
// Inputs: d_in[0]=x [B,T,F_IN] f32, d_in[1]=W1 [H,F_IN] f32, d_in[2]=W2 [OUT,H] f32
// Output: concat(com_spk [B,T,OUT], ch_spk [B,T,H], x [B,T,F_IN]) f32
// Pipeline: sA = phaseA groups; sB = memcpy + phaseB groups (after eA[g]);
// default = init/transpose + steps per group (after eB[g]).
// ---------------------------------------------------------------------------
extern "C" void kernel_launch(void* const* d_in, const int* in_sizes, int n_in,
                              void* d_out, int out_size)
{
    const float* x  = (const float*)d_in[0];
    const float* W1 = (const float*)d_in[1];
    const float* W2 = (const float*)d_in[2];
    float* out = (float*)d_out;

    const size_t COM_OFF = 0;
    const size_t CH_OFF  = (size_t)BT * OUT_SZ;
    const size_t X_OFF   = CH_OFF + (size_t)BT * H_SZ;

    float* out_com = out + COM_OFF;
    float* out_ch  = out + CH_OFF;
    float* out_x   = out + X_OFF;

    float* g_H_p;
    cudaGetSymbolAddress((void**)&g_H_p, g_H);

    // ---- fork both side streams from origin ----
    cudaEventRecord(g_pr.ev_fork, 0);
    cudaStreamWaitEvent(g_pr.sA, g_pr.ev_fork, 0);
    cudaStreamWaitEvent(g_pr.sB, g_pr.ev_fork, 0);

    // stream A: phase A per t-group, eager
    {
        dim3 grid(H_SZ / G1_BN, ROWS_PER_G / G1_BM);   // (16, 16) = 256 CTAs
        for (int g = 0; g < N_GROUPS; g++) {
            gemm1_phase_kernel<false><<<grid, 256, 0, g_pr.sA>>>(
                x, W1, g_H_p, 0, g * ROWS_PER_G);
            cudaEventRecord(g_pr.eA[g], g_pr.sA);
        }
    }

    // stream B: x passthrough (fills the A0 window), then phase B per group
    {
        cudaMemcpyAsync(out_x, x, (size_t)BT * F_IN * sizeof(float),
                        cudaMemcpyDeviceToDevice, g_pr.sB);
        dim3 grid(H_SZ / G1_BN, ROWS_PER_G / G1_BM);
        for (int g = 0; g < N_GROUPS; g++) {
            cudaStreamWaitEvent(g_pr.sB, g_pr.eA[g], 0);
            gemm1_phase_kernel<true><<<grid, 256, 0, g_pr.sB>>>(
                x, W1, g_H_p, G1_KC, g * ROWS_PER_G);
            cudaEventRecord(g_pr.eB[g], g_pr.sB);
        }
    }

    // default: init + transpose, then steps as groups complete
    {
        size_t n = (size_t)B_SZ * H_SZ;
        init_state_kernel<<<(unsigned)((n + 255) / 256), 256>>>();
        dim3 tgrid(H_SZ / 32, OUT_SZ / 32);
        transpose_w2_kernel<<<tgrid, dim3(32, 8)>>>(W2);
    }
    for (int g = 0; g < N_GROUPS; g++) {
        cudaStreamWaitEvent(0, g_pr.eB[g], 0);
        for (int t = g * T_PER_G; t < (g + 1) * T_PER_G; t++)
            step_kernel<<<B_SZ, 256>>>(t, out_ch, out_com);
    }

    // join stream A (B already joined via eB[last] -> default)
    cudaStreamWaitEvent(0, g_pr.eA[N_GROUPS - 1], 0);

    (void)in_sizes; (void)n_in; (void)out_size;
}